// round 16
// baseline (speedup 1.0000x reference)
#include <cuda_runtime.h>
#include <cuda_fp16.h>
#include <cstdint>

// ---------------------------------------------------------------------------
// QuadConv via baseline-PTX fp16 mma.sync m16n8k16 + ldmatrix (compute_103).
//
//   out[N,128] = concat_k( F[idx[:,k]] ) @ W^T + b
//   N=262144, C_IN=C_OUT=128, K=9 -> GEMM M=N, N=128, K=1152 (A row-gathered).
//   neigh_idx is int32 on the wire.
//
// R15: B bypasses smem entirely. m16n8k16 B fragment regs are 4B words of
// contiguous k in the [n][k] W16 layout -> loaded with plain LDG.32 from
// global (L1-hot: every CTA reads the same 16KB chunk; addresses fold into
// immediates). Frees 36.9KB smem -> A stage KB 64 -> 128 (one neighbor per
// stage, 9 stages). Deletes per stage: 8 B-cp.async/thread, 16 B-ldmatrix/
// warp, 16KB smem round-trip. Same k order -> rel_err unchanged.
// Base otherwise = R14 (3 CTAs/SM, 4 warps 2x2, 64x64 warp tiles).
// ---------------------------------------------------------------------------

namespace qc {
constexpr int NPTS   = 262144;
constexpr int CIN    = 128;
constexpr int COUT   = 128;
constexpr int KNB    = 9;
constexpr int KTOT   = KNB * CIN;      // 1152
constexpr int KB     = 128;            // k per pipeline stage = one neighbor
constexpr int NKB    = KTOT / KB;      // 9 stages
constexpr int MTILE  = 128;
constexpr int CTAS   = NPTS / MTILE;   // 2048
constexpr int THREADS = 128;           // 4 warps

constexpr int ROWPAD = 136;            // halves per A smem row (128 + 8 pad = 272B)
                                       // ldmatrix phase banks: 68r mod 32 = 4r distinct
constexpr int A_HALF = MTILE * ROWPAD;          // 17408 halves per buffer
constexpr int SMEM_HALVES = 2 * A_HALF;         // 34816
constexpr int SMEM_BYTES  = SMEM_HALVES * 2;    // 69,632 -> 3 CTAs/SM
} // namespace qc

// fp16 copies of F and W, produced once per launch by pre-kernels.
__device__ __half F16[qc::NPTS * qc::CIN];      // 64 MB static
__device__ __half W16[qc::COUT * qc::KTOT];     // 288 KB static

// ------------------------------ PTX helpers -------------------------------

__device__ __forceinline__ uint32_t smem_u32(const void* p) {
    return (uint32_t)__cvta_generic_to_shared(p);
}

__device__ __forceinline__ uint32_t h2_as_u32(__half2 h) {
    uint32_t u;
    memcpy(&u, &h, 4);
    return u;
}

__device__ __forceinline__ void cp_async16(uint32_t dst, const void* src, int src_size) {
    asm volatile("cp.async.cg.shared.global [%0], [%1], 16, %2;"
                 ::"r"(dst), "l"(src), "r"(src_size) : "memory");
}
__device__ __forceinline__ void cp_commit() {
    asm volatile("cp.async.commit_group;" ::: "memory");
}
template <int N>
__device__ __forceinline__ void cp_wait() {
    asm volatile("cp.async.wait_group %0;" ::"n"(N) : "memory");
}

__device__ __forceinline__ void ldmatrix_x4(uint32_t& r0, uint32_t& r1,
                                            uint32_t& r2, uint32_t& r3, uint32_t addr) {
    asm volatile("ldmatrix.sync.aligned.m8n8.x4.shared.b16 {%0,%1,%2,%3}, [%4];"
                 : "=r"(r0), "=r"(r1), "=r"(r2), "=r"(r3) : "r"(addr));
}

__device__ __forceinline__ void mma_f16(float& c0, float& c1, float& c2, float& c3,
                                        uint32_t a0, uint32_t a1, uint32_t a2, uint32_t a3,
                                        uint32_t b0, uint32_t b1) {
    asm volatile(
        "mma.sync.aligned.m16n8k16.row.col.f32.f16.f16.f32 "
        "{%0,%1,%2,%3}, {%4,%5,%6,%7}, {%8,%9}, {%0,%1,%2,%3};"
        : "+f"(c0), "+f"(c1), "+f"(c2), "+f"(c3)
        : "r"(a0), "r"(a1), "r"(a2), "r"(a3), "r"(b0), "r"(b1));
}

// ----------------- pre-kernels: F, W -> fp16 (RNE) -------------------------

__global__ void __launch_bounds__(256) fconv_kernel(const float* __restrict__ F) {
    size_t i = (size_t)blockIdx.x * 256 + threadIdx.x;   // one float4 each
    const float4 v = ((const float4*)F)[i];
    __half2 h0 = __floats2half2_rn(v.x, v.y);
    __half2 h1 = __floats2half2_rn(v.z, v.w);
    ((uint2*)F16)[i] = make_uint2(h2_as_u32(h0), h2_as_u32(h1));
}

__global__ void __launch_bounds__(256) wconv_kernel(const float* __restrict__ W) {
    size_t i = (size_t)blockIdx.x * 256 + threadIdx.x;
    if (i < (size_t)qc::COUT * qc::KTOT / 4) {
        const float4 v = ((const float4*)W)[i];
        __half2 h0 = __floats2half2_rn(v.x, v.y);
        __half2 h1 = __floats2half2_rn(v.z, v.w);
        ((uint2*)W16)[i] = make_uint2(h2_as_u32(h0), h2_as_u32(h1));
    }
}

// ------------------------------- kernel -----------------------------------

__global__ void __launch_bounds__(qc::THREADS, 3)
quadconv_mma_kernel(const int* __restrict__ NIDX,
                    const float* __restrict__ BIAS,
                    float* __restrict__ OUT) {
    using namespace qc;
    extern __shared__ __half smh[];
    const uint32_t sA_u = smem_u32(smh);

    const int tid  = threadIdx.x;
    const int wid  = tid >> 5;    // 0..3
    const int lane = tid & 31;
    const int g    = lane >> 2;   // 0..7
    const int klo  = lane & 3;    // 0..3
    const int gb   = blockIdx.x * MTILE;

    // ---- per-thread loader coordinates & register-cached indices -----------
    // 128 rows x 256B per stage = 2048 chunks of 16B. Each thread: 8 rows
    // (lrow + 16i) x 2 consecutive 16B segs (32B contiguous per row).
    const int lrow  = tid >> 3;   // 0..15
    const int lseg2 = (tid & 7) * 2;  // 0,2,..,14 (16B-seg index, 2 per thread)
    int idxr[8];
    auto refresh_idx = [&](int kn) {
#pragma unroll
        for (int i = 0; i < 8; i++)
            idxr[i] = NIDX[(size_t)(gb + lrow + i * 16) * KNB + kn];
    };

    // A gather for stage kb (= neighbor kb), full 128-half rows, zfill OOB.
    auto load_tiles = [&](int buf) {
#pragma unroll
        for (int i = 0; i < 8; i++) {
            int row = lrow + i * 16;
            int nb  = idxr[i];
            bool ok = (unsigned)nb < (unsigned)NPTS;
            const __half* src = F16 + (size_t)(ok ? nb : 0) * CIN + lseg2 * 8;
            uint32_t dst = sA_u + (uint32_t)(buf * A_HALF + row * ROWPAD + lseg2 * 8) * 2;
            cp_async16(dst,      src,     ok ? 16 : 0);
            cp_async16(dst + 16, src + 8, ok ? 16 : 0);
        }
    };

    // ---- warp tiling: 4 warps 2x2, warp tile 64(M) x 64(N) -----------------
    const int Mbase = (wid >> 1) * 64;
    const int Nbase = (wid & 1) * 64;
    float acc[4][8][4];
#pragma unroll
    for (int mf = 0; mf < 4; mf++)
#pragma unroll
        for (int nf = 0; nf < 8; nf++)
#pragma unroll
            for (int q = 0; q < 4; q++) acc[mf][nf][q] = 0.f;

    // ---- A ldmatrix per-lane base offsets (bytes, buffer-relative) ---------
    // A x4: m=lane>>3 -> {r0-7/k0-7, r8-15/k0-7, r0-7/k8-15, r8-15/k8-15}
    const int a_rit = (lane & 7) + ((lane >> 3) & 1) * 8;
    const int a_k8  = (lane >> 4) * 8;             // halves
    uint32_t aoff[4];
#pragma unroll
    for (int mf = 0; mf < 4; mf++)
        aoff[mf] = (uint32_t)(((Mbase + mf * 16 + a_rit) * ROWPAD + a_k8) * 2);

    // ---- B base pointer: fragment words are contiguous-k 4B loads ----------
    // b0(nf,s) = W16[(Nbase+nf*8+g)*KTOT + kb*128 + s*16 + 2*klo], b1 = +8.
    // nf/s are compile-time in the unrolled loop -> immediate offsets.
    const __half* wbase = W16 + (size_t)(Nbase + g) * KTOT + 2 * klo;

    // ---- prologue -----------------------------------------------------------
    refresh_idx(0);
    load_tiles(0);
    cp_commit();

    // ---- main K loop: 9 stages, one neighbor each ----------------------------
    for (int kb = 0; kb < NKB; kb++) {
        const int buf = kb & 1;
        if (kb + 1 < NKB) {
            refresh_idx(kb + 1);
            load_tiles(buf ^ 1);
            cp_commit();
            cp_wait<1>();
        } else {
            cp_wait<0>();
        }
        __syncthreads();   // cross-thread visibility of buf's tile

        const uint32_t abuf = sA_u + (uint32_t)(buf * A_HALF) * 2;
        const __half*  wk   = wbase + kb * KB;

#pragma unroll
        for (int s = 0; s < 8; s++) {          // 8 k-steps of 16
            uint32_t afr[4][4];
#pragma unroll
            for (int mf = 0; mf < 4; mf++)
                ldmatrix_x4(afr[mf][0], afr[mf][1], afr[mf][2], afr[mf][3],
                            abuf + aoff[mf] + s * 32);   // 16 halves = 32B
            // B direct from global (L1-hot, immediate offsets)
#pragma unroll
            for (int nf = 0; nf < 8; nf++) {
                const __half* wp = wk + nf * 8 * KTOT + s * 16;
                uint32_t b0 = *(const uint32_t*)(wp);
                uint32_t b1 = *(const uint32_t*)(wp + 8);
#pragma unroll
                for (int mf = 0; mf < 4; mf++)
                    mma_f16(acc[mf][nf][0], acc[mf][nf][1],
                            acc[mf][nf][2], acc[mf][nf][3],
                            afr[mf][0], afr[mf][1], afr[mf][2], afr[mf][3],
                            b0, b1);
            }
        }
        __syncthreads();   // all reads of buf done before kb+2 overwrites it
    }

    // ---- epilogue: add bias (global, L2-hot), float2 stores -----------------
#pragma unroll
    for (int mf = 0; mf < 4; mf++) {
#pragma unroll
        for (int nf = 0; nf < 8; nf++) {
            int col  = Nbase + nf * 8 + 2 * klo;
            float bx = __ldg(BIAS + col), by = __ldg(BIAS + col + 1);
            size_t r0 = (size_t)(gb + Mbase + mf * 16 + g) * COUT + col;
            size_t r1 = r0 + (size_t)8 * COUT;
            float2 v0 = make_float2(acc[mf][nf][0] + bx, acc[mf][nf][1] + by);
            float2 v1 = make_float2(acc[mf][nf][2] + bx, acc[mf][nf][3] + by);
            *(float2*)(OUT + r0) = v0;
            *(float2*)(OUT + r1) = v1;
        }
    }
}

// ----------------------------- launch glue --------------------------------

extern "C" void kernel_launch(void* const* d_in, const int* in_sizes, int n_in,
                              void* d_out, int out_size) {
    using namespace qc;
    const float* F = (const float*)d_in[0];
    const int*   I = (const int*)d_in[1];
    const float* W = (const float*)d_in[2];
    const float* B = (const float*)d_in[3];
    for (int i = 0; i < n_in; i++) {
        switch (in_sizes[i]) {
            case NPTS * CIN:       F = (const float*)d_in[i]; break;      // 33554432
            case NPTS * KNB:       I = (const int*)d_in[i];   break;      // 2359296
            case COUT * KNB * CIN: W = (const float*)d_in[i]; break;      // 147456
            case COUT:             B = (const float*)d_in[i]; break;      // 128
            default: break;
        }
    }
    fconv_kernel<<<(NPTS * CIN / 4) / 256, 256>>>(F);                 // 32768 blocks
    wconv_kernel<<<((COUT * KTOT / 4) + 255) / 256, 256>>>(W);
    cudaFuncSetAttribute(quadconv_mma_kernel,
                         cudaFuncAttributeMaxDynamicSharedMemorySize, SMEM_BYTES);
    quadconv_mma_kernel<<<CTAS, THREADS, SMEM_BYTES>>>(I, B, (float*)d_out);
}

// round 17
// speedup vs baseline: 2.4300x; 2.4300x over previous
#include <cuda_runtime.h>
#include <cuda_fp16.h>
#include <cstdint>

// ---------------------------------------------------------------------------
// QuadConv via baseline-PTX fp16 mma.sync m16n8k16 + ldmatrix (compute_103).
//
//   out[N,128] = concat_k( F[idx[:,k]] ) @ W^T + b
//   N=262144, C_IN=C_OUT=128, K=9 -> GEMM M=N, N=128, K=1152 (A row-gathered).
//   neigh_idx is int32 on the wire.
//
// R16: 4 barrier domains per SM. R15 (B via direct LDG) regressed 2.4x —
// reverted; B back in smem via cp.async. Domain scaling is the proven lever
// (1->2: -20%, 2->3: -8%), so: MTILE 128->64, 4096 CTAs, 4 warps (32x64
// warp tiles), launch_bounds(128,4); smem 55.3KB -> 4 CTAs/SM. KB=64 per
// stage (18 stages) as in R14. F/W pre-converted to fp16 once per launch.
// ---------------------------------------------------------------------------

namespace qc {
constexpr int NPTS   = 262144;
constexpr int CIN    = 128;
constexpr int COUT   = 128;
constexpr int KNB    = 9;
constexpr int KTOT   = KNB * CIN;      // 1152
constexpr int KB     = 64;             // k per pipeline stage
constexpr int NKB    = KTOT / KB;      // 18 stages
constexpr int MTILE  = 64;
constexpr int CTAS   = NPTS / MTILE;   // 4096
constexpr int THREADS = 128;           // 4 warps

constexpr int ROWPAD = 72;             // halves per smem row (64 + 8 pad = 144B)
constexpr int A_HALF = MTILE * ROWPAD;          // 4608 halves per buffer
constexpr int B_HALF = COUT * ROWPAD;           // 9216
constexpr int OFF_A  = 0;                       // 2 buffers
constexpr int OFF_B  = 2 * A_HALF;              // 2 buffers
constexpr int SMEM_HALVES = OFF_B + 2 * B_HALF; // 27648
constexpr int SMEM_BYTES  = SMEM_HALVES * 2;    // 55,296 -> 4 CTAs/SM
} // namespace qc

// fp16 copies of F and W, produced once per launch by pre-kernels.
__device__ __half F16[qc::NPTS * qc::CIN];      // 64 MB static
__device__ __half W16[qc::COUT * qc::KTOT];     // 288 KB static

// ------------------------------ PTX helpers -------------------------------

__device__ __forceinline__ uint32_t smem_u32(const void* p) {
    return (uint32_t)__cvta_generic_to_shared(p);
}

__device__ __forceinline__ uint32_t h2_as_u32(__half2 h) {
    uint32_t u;
    memcpy(&u, &h, 4);
    return u;
}

__device__ __forceinline__ void cp_async16(uint32_t dst, const void* src, int src_size) {
    asm volatile("cp.async.cg.shared.global [%0], [%1], 16, %2;"
                 ::"r"(dst), "l"(src), "r"(src_size) : "memory");
}
__device__ __forceinline__ void cp_commit() {
    asm volatile("cp.async.commit_group;" ::: "memory");
}
template <int N>
__device__ __forceinline__ void cp_wait() {
    asm volatile("cp.async.wait_group %0;" ::"n"(N) : "memory");
}

__device__ __forceinline__ void ldmatrix_x4(uint32_t& r0, uint32_t& r1,
                                            uint32_t& r2, uint32_t& r3, uint32_t addr) {
    asm volatile("ldmatrix.sync.aligned.m8n8.x4.shared.b16 {%0,%1,%2,%3}, [%4];"
                 : "=r"(r0), "=r"(r1), "=r"(r2), "=r"(r3) : "r"(addr));
}

__device__ __forceinline__ void mma_f16(float& c0, float& c1, float& c2, float& c3,
                                        uint32_t a0, uint32_t a1, uint32_t a2, uint32_t a3,
                                        uint32_t b0, uint32_t b1) {
    asm volatile(
        "mma.sync.aligned.m16n8k16.row.col.f32.f16.f16.f32 "
        "{%0,%1,%2,%3}, {%4,%5,%6,%7}, {%8,%9}, {%0,%1,%2,%3};"
        : "+f"(c0), "+f"(c1), "+f"(c2), "+f"(c3)
        : "r"(a0), "r"(a1), "r"(a2), "r"(a3), "r"(b0), "r"(b1));
}

// ----------------- pre-kernels: F, W -> fp16 (RNE) -------------------------

__global__ void __launch_bounds__(256) fconv_kernel(const float* __restrict__ F) {
    size_t i = (size_t)blockIdx.x * 256 + threadIdx.x;   // one float4 each
    const float4 v = ((const float4*)F)[i];
    __half2 h0 = __floats2half2_rn(v.x, v.y);
    __half2 h1 = __floats2half2_rn(v.z, v.w);
    ((uint2*)F16)[i] = make_uint2(h2_as_u32(h0), h2_as_u32(h1));
}

__global__ void __launch_bounds__(256) wconv_kernel(const float* __restrict__ W) {
    size_t i = (size_t)blockIdx.x * 256 + threadIdx.x;
    if (i < (size_t)qc::COUT * qc::KTOT / 4) {
        const float4 v = ((const float4*)W)[i];
        __half2 h0 = __floats2half2_rn(v.x, v.y);
        __half2 h1 = __floats2half2_rn(v.z, v.w);
        ((uint2*)W16)[i] = make_uint2(h2_as_u32(h0), h2_as_u32(h1));
    }
}

// ------------------------------- kernel -----------------------------------

__global__ void __launch_bounds__(qc::THREADS, 4)
quadconv_mma_kernel(const int* __restrict__ NIDX,
                    const float* __restrict__ BIAS,
                    float* __restrict__ OUT) {
    using namespace qc;
    extern __shared__ __half smh[];
    const uint32_t sA_u = smem_u32(smh + OFF_A);
    const uint32_t sB_u = smem_u32(smh + OFF_B);

    const int tid  = threadIdx.x;
    const int wid  = tid >> 5;    // 0..3
    const int lane = tid & 31;
    const int g    = lane >> 2;   // 0..7
    const int klo  = lane & 3;    // 0..3
    const int gb   = blockIdx.x * MTILE;

    // ---- per-thread loader coordinates & register-cached indices -----------
    const int lrow = tid >> 3;    // 0..15
    const int lseg = tid & 7;     // 0..7 (16B chunks; KB=64 halves = 128B/row)
    int idxr[4];                  // neighbor index for rows lrow+16i (64 rows)
    auto refresh_idx = [&](int kn) {
#pragma unroll
        for (int i = 0; i < 4; i++)
            idxr[i] = NIDX[(size_t)(gb + lrow + i * 16) * KNB + kn];
    };

    // A gather (zfill OOB) + B (W chunk), both already fp16.
    // kb indexes 64-wide K chunks; kn = kb>>1, col offset = (kb&1)*64.
    auto load_tiles = [&](int kb, int buf) {
        const int coff = (kb & 1) * 64;
#pragma unroll
        for (int i = 0; i < 4; i++) {              // A: 512 chunks / 128 thr
            int row = lrow + i * 16;
            int nb  = idxr[i];
            bool ok = (unsigned)nb < (unsigned)NPTS;
            const __half* src = F16 + (size_t)(ok ? nb : 0) * CIN + coff + lseg * 8;
            cp_async16(sA_u + (uint32_t)(buf * A_HALF + row * ROWPAD + lseg * 8) * 2,
                       src, ok ? 16 : 0);
        }
#pragma unroll
        for (int i = 0; i < 8; i++) {              // B: 1024 chunks / 128 thr
            int n = lrow + i * 16;
            const __half* src = W16 + (size_t)n * KTOT + kb * 64 + lseg * 8;
            cp_async16(sB_u + (uint32_t)(buf * B_HALF + n * ROWPAD + lseg * 8) * 2,
                       src, 16);
        }
    };

    // ---- warp tiling: 4 warps 2x2, warp tile 32(M) x 64(N) -----------------
    const int Mbase = (wid >> 1) * 32;
    const int Nbase = (wid & 1) * 64;
    float acc[2][8][4];
#pragma unroll
    for (int mf = 0; mf < 2; mf++)
#pragma unroll
        for (int nf = 0; nf < 8; nf++)
#pragma unroll
            for (int q = 0; q < 4; q++) acc[mf][nf][q] = 0.f;

    // ---- ldmatrix per-lane base offsets (bytes, buffer-relative) -----------
    const int a_rit = (lane & 7) + ((lane >> 3) & 1) * 8;
    const int a_k8  = (lane >> 4) * 8;             // halves
    uint32_t aoff[2];
#pragma unroll
    for (int mf = 0; mf < 2; mf++)
        aoff[mf] = (uint32_t)(((Mbase + mf * 16 + a_rit) * ROWPAD + a_k8) * 2);
    const int b_nr = ((lane >> 4) & 1) * 8 + (lane & 7);
    const int b_k8 = ((lane >> 3) & 1) * 8;
    uint32_t boff[4];
#pragma unroll
    for (int p = 0; p < 4; p++)
        boff[p] = (uint32_t)(((Nbase + p * 16 + b_nr) * ROWPAD + b_k8) * 2);

    // ---- prologue -----------------------------------------------------------
    refresh_idx(0);
    int kn_cur = 0;
    load_tiles(0, 0);
    cp_commit();

    // ---- main K loop (loads first, then wait, then mma) ---------------------
    for (int kb = 0; kb < NKB; kb++) {
        const int buf = kb & 1;
        const int pf  = kb + 1;
        if (pf < NKB) {
            const int knp = pf >> 1;
            if (knp != kn_cur) { kn_cur = knp; refresh_idx(knp); }
            load_tiles(pf, buf ^ 1);
            cp_commit();
            cp_wait<1>();
        } else {
            cp_wait<0>();
        }
        __syncthreads();   // cross-thread visibility of buf's tiles

        const uint32_t abuf = sA_u + (uint32_t)(buf * A_HALF) * 2;
        const uint32_t bbuf = sB_u + (uint32_t)(buf * B_HALF) * 2;

#pragma unroll
        for (int s = 0; s < 4; s++) {          // 4 k-steps of 16
            uint32_t afr[2][4];
#pragma unroll
            for (int mf = 0; mf < 2; mf++)
                ldmatrix_x4(afr[mf][0], afr[mf][1], afr[mf][2], afr[mf][3],
                            abuf + aoff[mf] + s * 32);   // 16 halves = 32B
            // lazy B: one ldmatrix per 16-n pair, immediately consumed
#pragma unroll
            for (int p = 0; p < 4; p++) {
                uint32_t b0a, b0b, b1a, b1b;   // nf=2p:{b0a,b0b}, nf=2p+1:{b1a,b1b}
                ldmatrix_x4(b0a, b0b, b1a, b1b, bbuf + boff[p] + s * 32);
#pragma unroll
                for (int mf = 0; mf < 2; mf++) {
                    mma_f16(acc[mf][2 * p][0], acc[mf][2 * p][1],
                            acc[mf][2 * p][2], acc[mf][2 * p][3],
                            afr[mf][0], afr[mf][1], afr[mf][2], afr[mf][3],
                            b0a, b0b);
                    mma_f16(acc[mf][2 * p + 1][0], acc[mf][2 * p + 1][1],
                            acc[mf][2 * p + 1][2], acc[mf][2 * p + 1][3],
                            afr[mf][0], afr[mf][1], afr[mf][2], afr[mf][3],
                            b1a, b1b);
                }
            }
        }
        __syncthreads();   // all reads of buf done before kb+2 overwrites it
    }

    // ---- epilogue: add bias (global, L2-hot), float2 stores -----------------
#pragma unroll
    for (int mf = 0; mf < 2; mf++) {
#pragma unroll
        for (int nf = 0; nf < 8; nf++) {
            int col  = Nbase + nf * 8 + 2 * klo;
            float bx = __ldg(BIAS + col), by = __ldg(BIAS + col + 1);
            size_t r0 = (size_t)(gb + Mbase + mf * 16 + g) * COUT + col;
            size_t r1 = r0 + (size_t)8 * COUT;
            float2 v0 = make_float2(acc[mf][nf][0] + bx, acc[mf][nf][1] + by);
            float2 v1 = make_float2(acc[mf][nf][2] + bx, acc[mf][nf][3] + by);
            *(float2*)(OUT + r0) = v0;
            *(float2*)(OUT + r1) = v1;
        }
    }
}

// ----------------------------- launch glue --------------------------------

extern "C" void kernel_launch(void* const* d_in, const int* in_sizes, int n_in,
                              void* d_out, int out_size) {
    using namespace qc;
    const float* F = (const float*)d_in[0];
    const int*   I = (const int*)d_in[1];
    const float* W = (const float*)d_in[2];
    const float* B = (const float*)d_in[3];
    for (int i = 0; i < n_in; i++) {
        switch (in_sizes[i]) {
            case NPTS * CIN:       F = (const float*)d_in[i]; break;      // 33554432
            case NPTS * KNB:       I = (const int*)d_in[i];   break;      // 2359296
            case COUT * KNB * CIN: W = (const float*)d_in[i]; break;      // 147456
            case COUT:             B = (const float*)d_in[i]; break;      // 128
            default: break;
        }
    }
    fconv_kernel<<<(NPTS * CIN / 4) / 256, 256>>>(F);                 // 32768 blocks
    wconv_kernel<<<((COUT * KTOT / 4) + 255) / 256, 256>>>(W);
    cudaFuncSetAttribute(quadconv_mma_kernel,
                         cudaFuncAttributeMaxDynamicSharedMemorySize, SMEM_BYTES);
    quadconv_mma_kernel<<<CTAS, THREADS, SMEM_BYTES>>>(I, B, (float*)d_out);
}